// round 1
// baseline (speedup 1.0000x reference)
#include <cuda_runtime.h>
#include <cuda_bf16.h>

#define BSZ 4
#define NN  15135
#define FIN 8
#define HH  64
#define EE  302700
#define ETOT (EE + NN)          // edges + self loops = 317835
#define FCD 256
#define NLAY 3
#define NEG_SLOPE 0.2f

// ---------------- scratch (device globals; no allocation) ----------------
__device__ float g_ht[BSZ * NN * HH];        // per-layer transformed features (pre-aggregation)
__device__ float g_es[BSZ * NN];
__device__ float g_ed[BSZ * NN];
__device__ float g_xs[NLAY][BSZ * NN * HH];  // relu'd layer outputs (kept for concat)
__device__ int   g_deg[NN];
__device__ int   g_off[NN + 1];
__device__ int   g_cursor[NN];
__device__ int   g_srcs[ETOT];               // CSR (grouped by dst): src node ids
__device__ float g_scores[BSZ * NN];
__device__ float g_h1[BSZ * FCD];

// ---------------- CSR build ----------------
__global__ void k_init(const float* __restrict__ lin1_b) {
    int i = blockIdx.x * blockDim.x + threadIdx.x;
    if (i < NN) { g_deg[i] = 1; g_cursor[i] = 0; }   // self-loop contributes 1
    if (i < BSZ * FCD) g_h1[i] = lin1_b[i & (FCD - 1)];
}

__global__ void k_count(const int* __restrict__ ei) {
    int i = blockIdx.x * blockDim.x + threadIdx.x;
    if (i < EE) atomicAdd(&g_deg[ei[EE + i]], 1);
}

__global__ void k_scan() {
    __shared__ int ssum[1024];
    const int CH = 15;   // 1024*15 = 15360 >= NN
    int t = threadIdx.x;
    int loc[CH];
    int lsum = 0;
    #pragma unroll
    for (int i = 0; i < CH; i++) {
        int g = t * CH + i;
        int d = (g < NN) ? g_deg[g] : 0;
        loc[i] = lsum;
        lsum += d;
    }
    ssum[t] = lsum;
    __syncthreads();
    for (int o = 1; o < 1024; o <<= 1) {
        int v = (t >= o) ? ssum[t - o] : 0;
        __syncthreads();
        ssum[t] += v;
        __syncthreads();
    }
    int base = ssum[t] - lsum;   // exclusive prefix
    #pragma unroll
    for (int i = 0; i < CH; i++) {
        int g = t * CH + i;
        if (g < NN) g_off[g] = base + loc[i];
    }
    if (t == 1023) g_off[NN] = ETOT;
}

__global__ void k_scatter(const int* __restrict__ ei) {
    int i = blockIdx.x * blockDim.x + threadIdx.x;
    if (i < EE) {
        int s = ei[i], d = ei[EE + i];
        int pos = g_off[d] + atomicAdd(&g_cursor[d], 1);
        g_srcs[pos] = s;
    } else if (i < ETOT) {
        int n = i - EE;
        int pos = g_off[n] + atomicAdd(&g_cursor[n], 1);
        g_srcs[pos] = n;   // self loop
    }
}

// ---------------- GAT layer: linear + attention scalars ----------------
// one block (64 threads) per (b,n); m = b*NN + n
__global__ void k_linear(const float* __restrict__ x0, int layer,
                         const float* __restrict__ W,
                         const float* __restrict__ asrc,
                         const float* __restrict__ adst) {
    int m = blockIdx.x;
    int t = threadIdx.x;
    if (m >= BSZ * NN) return;

    __shared__ float sx[HH];
    __shared__ float ss[HH];
    __shared__ float sd[HH];

    int fin = (layer == 0) ? FIN : HH;
    const float* xin = (layer == 0) ? x0 : g_xs[layer - 1];
    const float* xr = xin + (size_t)m * fin;
    if (t < fin) sx[t] = xr[t];
    __syncthreads();

    float acc = 0.f;
    if (layer == 0) {
        #pragma unroll
        for (int f = 0; f < FIN; f++) acc += sx[f] * W[f * HH + t];
    } else {
        #pragma unroll
        for (int f = 0; f < HH; f++) acc += sx[f] * W[f * HH + t];
    }
    g_ht[(size_t)m * HH + t] = acc;

    ss[t] = acc * asrc[t];
    sd[t] = acc * adst[t];
    __syncthreads();
    if (t < 32) {
        float v1 = ss[t] + ss[t + 32];
        float v2 = sd[t] + sd[t + 32];
        #pragma unroll
        for (int o = 16; o; o >>= 1) {
            v1 += __shfl_down_sync(0xffffffffu, v1, o);
            v2 += __shfl_down_sync(0xffffffffu, v2, o);
        }
        if (t == 0) { g_es[m] = v1; g_ed[m] = v2; }
    }
}

// ---------------- softmax-weighted aggregation: one warp per (b, dst) ----------------
__global__ void k_aggr(int layer, const float* __restrict__ bias) {
    int gw = (blockIdx.x * blockDim.x + threadIdx.x) >> 5;
    int lane = threadIdx.x & 31;
    if (gw >= BSZ * NN) return;
    int b = gw / NN, n = gw - b * NN;
    int base = b * NN;
    int s0 = g_off[n], s1 = g_off[n + 1];
    float edn = g_ed[base + n];

    // pass 1: max
    float mx = -1e30f;
    for (int j = s0 + lane; j < s1; j += 32) {
        int s = g_srcs[j];
        float e = g_es[base + s] + edn;
        e = (e > 0.f) ? e : NEG_SLOPE * e;
        mx = fmaxf(mx, e);
    }
    #pragma unroll
    for (int o = 16; o; o >>= 1) mx = fmaxf(mx, __shfl_xor_sync(0xffffffffu, mx, o));

    // pass 1b: denom
    float den = 0.f;
    for (int j = s0 + lane; j < s1; j += 32) {
        int s = g_srcs[j];
        float e = g_es[base + s] + edn;
        e = (e > 0.f) ? e : NEG_SLOPE * e;
        den += __expf(e - mx);
    }
    #pragma unroll
    for (int o = 16; o; o >>= 1) den += __shfl_xor_sync(0xffffffffu, den, o);
    float inv = 1.f / den;

    // pass 2: weighted gather (serial over neighbors, lanes over channels)
    float2 acc = make_float2(0.f, 0.f);
    for (int j = s0; j < s1; j++) {
        int s = g_srcs[j];                       // broadcast load
        float e = g_es[base + s] + edn;          // broadcast load
        e = (e > 0.f) ? e : NEG_SLOPE * e;
        float w = __expf(e - mx) * inv;
        const float2* hp = (const float2*)(g_ht + (size_t)(base + s) * HH);
        float2 hv = hp[lane];                    // coalesced 256B per warp
        acc.x += w * hv.x;
        acc.y += w * hv.y;
    }
    float o0 = fmaxf(acc.x + bias[2 * lane], 0.f);
    float o1 = fmaxf(acc.y + bias[2 * lane + 1], 0.f);
    float2* op = (float2*)(g_xs[layer] + (size_t)gw * HH);
    op[lane] = make_float2(o0, o1);
}

// ---------------- readout: scores[b,n] = cat(xs)·fc_w + fc_b ----------------
// one warp per (b,n); concat index f = h*NLAY + layer
__global__ void k_scores(const float* __restrict__ fcw, const float* __restrict__ fcb) {
    int gw = (blockIdx.x * blockDim.x + threadIdx.x) >> 5;
    int lane = threadIdx.x & 31;
    if (gw >= BSZ * NN) return;
    float v = 0.f;
    #pragma unroll
    for (int ly = 0; ly < NLAY; ly++) {
        const float* xr = g_xs[ly] + (size_t)gw * HH;
        float a = xr[lane];
        float c = xr[lane + 32];
        v += a * fcw[lane * NLAY + ly];
        v += c * fcw[(lane + 32) * NLAY + ly];
    }
    #pragma unroll
    for (int o = 16; o; o >>= 1) v += __shfl_down_sync(0xffffffffu, v, o);
    if (lane == 0) g_scores[gw] = v + fcb[0];
}

// ---------------- lin1: h1[b,c] += sum_n scores[b,n] * lin1_w[n,c] ----------------
#define GRID1 148
__global__ void k_lin1(const float* __restrict__ w1) {
    int c = threadIdx.x;            // 0..255
    const int R = (NN + GRID1 - 1) / GRID1;
    int r0 = blockIdx.x * R;
    int r1 = min(r0 + R, NN);
    float a0 = 0.f, a1 = 0.f, a2 = 0.f, a3 = 0.f;
    for (int n = r0; n < r1; n++) {
        float w = w1[(size_t)n * FCD + c];
        a0 += g_scores[0 * NN + n] * w;
        a1 += g_scores[1 * NN + n] * w;
        a2 += g_scores[2 * NN + n] * w;
        a3 += g_scores[3 * NN + n] * w;
    }
    atomicAdd(&g_h1[0 * FCD + c], a0);
    atomicAdd(&g_h1[1 * FCD + c], a1);
    atomicAdd(&g_h1[2 * FCD + c], a2);
    atomicAdd(&g_h1[3 * FCD + c], a3);
}

// ---------------- final: relu, lin2, log_softmax ----------------
__global__ void k_final(const float* __restrict__ w2, const float* __restrict__ b2,
                        float* __restrict__ out) {
    int b = threadIdx.x >> 5;
    int lane = threadIdx.x & 31;
    if (b >= BSZ) return;
    float a0 = 0.f, a1 = 0.f;
    for (int c = lane; c < FCD; c += 32) {
        float hv = fmaxf(g_h1[b * FCD + c], 0.f);
        a0 += hv * w2[c * 2 + 0];
        a1 += hv * w2[c * 2 + 1];
    }
    #pragma unroll
    for (int o = 16; o; o >>= 1) {
        a0 += __shfl_down_sync(0xffffffffu, a0, o);
        a1 += __shfl_down_sync(0xffffffffu, a1, o);
    }
    if (lane == 0) {
        float l0 = a0 + b2[0];
        float l1 = a1 + b2[1];
        float m = fmaxf(l0, l1);
        float lse = m + logf(expf(l0 - m) + expf(l1 - m));
        out[b * 2 + 0] = l0 - lse;
        out[b * 2 + 1] = l1 - lse;
    }
}

// ---------------- host launch ----------------
extern "C" void kernel_launch(void* const* d_in, const int* in_sizes, int n_in,
                              void* d_out, int out_size) {
    const float* x    = (const float*)d_in[0];
    const int*   ei   = (const int*)d_in[1];
    const float* W[NLAY]  = {(const float*)d_in[3], (const float*)d_in[7],  (const float*)d_in[11]};
    const float* as[NLAY] = {(const float*)d_in[4], (const float*)d_in[8],  (const float*)d_in[12]};
    const float* ad[NLAY] = {(const float*)d_in[5], (const float*)d_in[9],  (const float*)d_in[13]};
    const float* bb[NLAY] = {(const float*)d_in[6], (const float*)d_in[10], (const float*)d_in[14]};
    const float* fcw  = (const float*)d_in[15];
    const float* fcb  = (const float*)d_in[16];
    const float* l1w  = (const float*)d_in[17];
    const float* l1b  = (const float*)d_in[18];
    const float* l2w  = (const float*)d_in[19];
    const float* l2b  = (const float*)d_in[20];
    float* out = (float*)d_out;

    k_init<<<(NN + 255) / 256, 256>>>(l1b);
    k_count<<<(EE + 255) / 256, 256>>>(ei);
    k_scan<<<1, 1024>>>();
    k_scatter<<<(ETOT + 255) / 256, 256>>>(ei);

    const int nwarps = BSZ * NN;
    const int aggr_blocks = (nwarps * 32 + 255) / 256;
    for (int l = 0; l < NLAY; l++) {
        k_linear<<<BSZ * NN, HH>>>(x, l, W[l], as[l], ad[l]);
        k_aggr<<<aggr_blocks, 256>>>(l, bb[l]);
    }

    k_scores<<<aggr_blocks, 256>>>(fcw, fcb);
    k_lin1<<<GRID1, FCD>>>(l1w);
    k_final<<<1, 128>>>(l2w, l2b, out);
}

// round 15
// speedup vs baseline: 1.2646x; 1.2646x over previous
#include <cuda_runtime.h>
#include <cuda_bf16.h>

#define BSZ 4
#define NN  15135
#define FIN 8
#define HH  64
#define EE  302700
#define ETOT (EE + NN)          // edges + self loops = 317835
#define FCD 256
#define NLAY 3
#define NEG_SLOPE 0.2f
#define FULLMASK 0xffffffffu

// ---------------- scratch (device globals; no allocation) ----------------
__device__ float g_ht[BSZ * NN * HH];        // per-layer transformed features (pre-aggregation)
__device__ float g_es[BSZ * NN];
__device__ float g_ed[BSZ * NN];
__device__ float g_xs[2][BSZ * NN * HH];     // relu'd outputs of layers 0,1 (layer 2 fused into scores)
__device__ int   g_deg[NN];
__device__ int   g_off[NN + 1];
__device__ int   g_cursor[NN];
__device__ int   g_srcs[ETOT];               // CSR (grouped by dst): src node ids
__device__ float g_scores[BSZ * NN];
__device__ float g_h1[BSZ * FCD];

// ---------------- CSR build ----------------
__global__ void k_init(const float* __restrict__ lin1_b) {
    int i = blockIdx.x * blockDim.x + threadIdx.x;
    if (i < NN) { g_deg[i] = 1; g_cursor[i] = 0; }   // self-loop contributes 1
    if (i < BSZ * FCD) g_h1[i] = lin1_b[i & (FCD - 1)];
}

__global__ void k_count(const int* __restrict__ ei) {
    int i = blockIdx.x * blockDim.x + threadIdx.x;
    if (i < EE) atomicAdd(&g_deg[ei[EE + i]], 1);
}

__global__ void k_scan() {
    __shared__ int ssum[1024];
    const int CH = 15;   // 1024*15 = 15360 >= NN
    int t = threadIdx.x;
    int loc[CH];
    int lsum = 0;
    #pragma unroll
    for (int i = 0; i < CH; i++) {
        int g = t * CH + i;
        int d = (g < NN) ? g_deg[g] : 0;
        loc[i] = lsum;
        lsum += d;
    }
    ssum[t] = lsum;
    __syncthreads();
    for (int o = 1; o < 1024; o <<= 1) {
        int v = (t >= o) ? ssum[t - o] : 0;
        __syncthreads();
        ssum[t] += v;
        __syncthreads();
    }
    int base = ssum[t] - lsum;   // exclusive prefix
    #pragma unroll
    for (int i = 0; i < CH; i++) {
        int g = t * CH + i;
        if (g < NN) g_off[g] = base + loc[i];
    }
    if (t == 1023) g_off[NN] = ETOT;
}

__global__ void k_scatter(const int* __restrict__ ei) {
    int i = blockIdx.x * blockDim.x + threadIdx.x;
    if (i < EE) {
        int s = ei[i], d = ei[EE + i];
        int pos = g_off[d] + atomicAdd(&g_cursor[d], 1);
        g_srcs[pos] = s;
    } else if (i < ETOT) {
        int n = i - EE;
        int pos = g_off[n] + atomicAdd(&g_cursor[n], 1);
        g_srcs[pos] = n;   // self loop
    }
}

// ---------------- GAT layer: linear + attention scalars ----------------
// 4 nodes per 256-thread block; BSZ*NN = 60540 = 15135 * 4 blocks exactly
__global__ void __launch_bounds__(256)
k_linear(const float* __restrict__ x0, int layer,
         const float* __restrict__ W,
         const float* __restrict__ asrc,
         const float* __restrict__ adst) {
    int local = threadIdx.x >> 6;     // 0..3
    int t = threadIdx.x & 63;
    int m = blockIdx.x * 4 + local;   // always < BSZ*NN

    __shared__ float sx[4][HH];
    __shared__ float ss[4][HH];
    __shared__ float sd[4][HH];

    int fin = (layer == 0) ? FIN : HH;
    const float* xin = (layer == 0) ? x0 : g_xs[layer - 1];
    if (t < fin) sx[local][t] = xin[(size_t)m * fin + t];
    __syncthreads();

    float acc = 0.f;
    if (layer == 0) {
        #pragma unroll
        for (int f = 0; f < FIN; f++) acc += sx[local][f] * W[f * HH + t];
    } else {
        #pragma unroll
        for (int f = 0; f < HH; f++) acc += sx[local][f] * W[f * HH + t];
    }
    g_ht[(size_t)m * HH + t] = acc;

    ss[local][t] = acc * asrc[t];
    sd[local][t] = acc * adst[t];
    __syncthreads();
    if (t < 32) {   // threads [0,32) of each 64-group = full warps 0,2,4,6
        float v1 = ss[local][t] + ss[local][t + 32];
        float v2 = sd[local][t] + sd[local][t + 32];
        #pragma unroll
        for (int o = 16; o; o >>= 1) {
            v1 += __shfl_down_sync(FULLMASK, v1, o);
            v2 += __shfl_down_sync(FULLMASK, v2, o);
        }
        if (t == 0) { g_es[m] = v1; g_ed[m] = v2; }
    }
}

// ---------------- softmax-weighted aggregation: one warp per (b, dst) ----------------
// Single pass: no max subtraction (exp args O(1), fp32-safe; softmax is
// shift-invariant), unnormalized accumulation with trailing divide.
// Chunked: 32 edges' weights computed in parallel (coalesced src loads,
// 1 exp/edge), then shfl-broadcast inner loop does coalesced 256B h gathers.
// LAST=1: layer 2 — fuse the fc readout (scores) and skip the xs store.
template <int LAST>
__global__ void __launch_bounds__(256)
k_aggr(int layer, const float* __restrict__ bias,
       const float* __restrict__ fcw, const float* __restrict__ fcb) {
    int gw = (blockIdx.x * blockDim.x + threadIdx.x) >> 5;
    int lane = threadIdx.x & 31;
    if (gw >= BSZ * NN) return;
    int b = gw / NN, n = gw - b * NN;
    int base = b * NN;
    int s0 = __ldg(&g_off[n]), s1 = __ldg(&g_off[n + 1]);
    float edn = __ldg(&g_ed[base + n]);

    float2 acc = make_float2(0.f, 0.f);
    float den = 0.f;

    for (int j0 = s0; j0 < s1; j0 += 32) {
        int cnt = min(32, s1 - j0);
        int s = 0;
        float w = 0.f;
        if (lane < cnt) {
            s = __ldg(&g_srcs[j0 + lane]);          // coalesced
            float e = __ldg(&g_es[base + s]) + edn; // random 4B gather
            e = (e > 0.f) ? e : NEG_SLOPE * e;
            w = __expf(e);
        }
        den += w;                                   // invalid lanes contribute 0

        #pragma unroll 4
        for (int k = 0; k < cnt; k++) {
            int   sk = __shfl_sync(FULLMASK, s, k);
            float wk = __shfl_sync(FULLMASK, w, k);
            const float2* hp = (const float2*)(g_ht + (size_t)(base + sk) * HH);
            float2 hv = __ldg(&hp[lane]);           // coalesced 256B per warp
            acc.x += wk * hv.x;
            acc.y += wk * hv.y;
        }
    }

    #pragma unroll
    for (int o = 16; o; o >>= 1) den += __shfl_xor_sync(FULLMASK, den, o);
    float inv = 1.f / den;

    int c0 = 2 * lane, c1 = 2 * lane + 1;
    float o0 = fmaxf(acc.x * inv + bias[c0], 0.f);
    float o1 = fmaxf(acc.y * inv + bias[c1], 0.f);

    if (!LAST) {
        float2* op = (float2*)(g_xs[layer] + (size_t)gw * HH);
        op[lane] = make_float2(o0, o1);
    } else {
        // fused readout: xcat channel f = c*NLAY + layer
        const float2* x0p = (const float2*)(g_xs[0] + (size_t)gw * HH);
        const float2* x1p = (const float2*)(g_xs[1] + (size_t)gw * HH);
        float2 v0 = x0p[lane];
        float2 v1 = x1p[lane];
        float v = o0 * fcw[c0 * NLAY + 2] + o1 * fcw[c1 * NLAY + 2]
                + v0.x * fcw[c0 * NLAY + 0] + v0.y * fcw[c1 * NLAY + 0]
                + v1.x * fcw[c0 * NLAY + 1] + v1.y * fcw[c1 * NLAY + 1];
        #pragma unroll
        for (int o = 16; o; o >>= 1) v += __shfl_down_sync(FULLMASK, v, o);
        if (lane == 0) g_scores[gw] = v + fcb[0];
    }
}

// ---------------- lin1: h1[b,c] += sum_n scores[b,n] * lin1_w[n,c] ----------------
#define GRID1 148
__global__ void __launch_bounds__(FCD)
k_lin1(const float* __restrict__ w1) {
    int c = threadIdx.x;            // 0..255
    const int R = (NN + GRID1 - 1) / GRID1;
    int r0 = blockIdx.x * R;
    int r1 = min(r0 + R, NN);
    float a0 = 0.f, a1 = 0.f, a2 = 0.f, a3 = 0.f;
    for (int n = r0; n < r1; n++) {
        float w = w1[(size_t)n * FCD + c];
        a0 += g_scores[0 * NN + n] * w;
        a1 += g_scores[1 * NN + n] * w;
        a2 += g_scores[2 * NN + n] * w;
        a3 += g_scores[3 * NN + n] * w;
    }
    atomicAdd(&g_h1[0 * FCD + c], a0);
    atomicAdd(&g_h1[1 * FCD + c], a1);
    atomicAdd(&g_h1[2 * FCD + c], a2);
    atomicAdd(&g_h1[3 * FCD + c], a3);
}

// ---------------- final: relu, lin2, log_softmax ----------------
__global__ void k_final(const float* __restrict__ w2, const float* __restrict__ b2,
                        float* __restrict__ out) {
    int b = threadIdx.x >> 5;
    int lane = threadIdx.x & 31;
    if (b >= BSZ) return;
    float a0 = 0.f, a1 = 0.f;
    for (int c = lane; c < FCD; c += 32) {
        float hv = fmaxf(g_h1[b * FCD + c], 0.f);
        a0 += hv * w2[c * 2 + 0];
        a1 += hv * w2[c * 2 + 1];
    }
    #pragma unroll
    for (int o = 16; o; o >>= 1) {
        a0 += __shfl_down_sync(FULLMASK, a0, o);
        a1 += __shfl_down_sync(FULLMASK, a1, o);
    }
    if (lane == 0) {
        float l0 = a0 + b2[0];
        float l1 = a1 + b2[1];
        float m = fmaxf(l0, l1);
        float lse = m + logf(expf(l0 - m) + expf(l1 - m));
        out[b * 2 + 0] = l0 - lse;
        out[b * 2 + 1] = l1 - lse;
    }
}

// ---------------- host launch ----------------
extern "C" void kernel_launch(void* const* d_in, const int* in_sizes, int n_in,
                              void* d_out, int out_size) {
    const float* x    = (const float*)d_in[0];
    const int*   ei   = (const int*)d_in[1];
    const float* W[NLAY]  = {(const float*)d_in[3], (const float*)d_in[7],  (const float*)d_in[11]};
    const float* as[NLAY] = {(const float*)d_in[4], (const float*)d_in[8],  (const float*)d_in[12]};
    const float* ad[NLAY] = {(const float*)d_in[5], (const float*)d_in[9],  (const float*)d_in[13]};
    const float* bb[NLAY] = {(const float*)d_in[6], (const float*)d_in[10], (const float*)d_in[14]};
    const float* fcw  = (const float*)d_in[15];
    const float* fcb  = (const float*)d_in[16];
    const float* l1w  = (const float*)d_in[17];
    const float* l1b  = (const float*)d_in[18];
    const float* l2w  = (const float*)d_in[19];
    const float* l2b  = (const float*)d_in[20];
    float* out = (float*)d_out;

    k_init<<<(NN + 255) / 256, 256>>>(l1b);
    k_count<<<(EE + 255) / 256, 256>>>(ei);
    k_scan<<<1, 1024>>>();
    k_scatter<<<(ETOT + 255) / 256, 256>>>(ei);

    const int lin_blocks = (BSZ * NN) / 4;        // 15135
    const int aggr_blocks = (BSZ * NN * 32 + 255) / 256;
    for (int l = 0; l < NLAY; l++) {
        k_linear<<<lin_blocks, 256>>>(x, l, W[l], as[l], ad[l]);
        if (l < NLAY - 1)
            k_aggr<0><<<aggr_blocks, 256>>>(l, bb[l], fcw, fcb);
        else
            k_aggr<1><<<aggr_blocks, 256>>>(l, bb[l], fcw, fcb);
    }

    k_lin1<<<GRID1, FCD>>>(l1w);
    k_final<<<1, 128>>>(l2w, l2b, out);
}